// round 1
// baseline (speedup 1.0000x reference)
#include <cuda_runtime.h>

#define NW        1024          // number of windows
#define TPW       256           // tokens per window (16x16)
#define CH        192           // channels
#define WIN_ELEMS (TPW*CH)      // 49152 floats per window per tensor

// Scratch (static device allocations are allowed; no runtime alloc).
__device__ float g_q[NW*WIN_ELEMS];
__device__ float g_k[NW*WIN_ELEMS];
__device__ float g_v[NW*WIN_ELEMS];
__device__ float g_lepe[NW*WIN_ELEMS];
__device__ float g_oa[NW*WIN_ELEMS];

// ---------------------------------------------------------------------------
// K1: QKV projection. C = gather(x) @ w_qkv^T + b_qkv
// M = 1024*256 = 262144, N = 576, K = 192. Tile 128x64x16, 256 threads,
// 8x4 micro-tile. Writes q/k/v scratch in [win][token][ch] layout.
// ---------------------------------------------------------------------------
__global__ __launch_bounds__(256) void qkv_kernel(
    const float* __restrict__ x,
    const float* __restrict__ wqkv,
    const float* __restrict__ bqkv)
{
    __shared__ float As[16][129];
    __shared__ float Bs[16][65];

    const int mtile = blockIdx.x;           // 0..2047
    const int ntile = blockIdx.y;           // 0..8
    const int win   = mtile >> 1;
    const int t0    = (mtile & 1) * 128;
    const int bb    = win >> 8;
    const int hy    = (win >> 4) & 15;
    const int wx    = win & 15;
    const int winbase = bb*12582912 + hy*786432 + wx*3072;
    const int n0    = ntile * 64;
    const int tid   = threadIdx.x;

    const int tm = (tid >> 4) * 8;          // 0..120
    const int tn = (tid & 15) * 4;          // 0..60

    float acc[8][4];
#pragma unroll
    for (int i = 0; i < 8; i++)
#pragma unroll
        for (int j = 0; j < 4; j++) acc[i][j] = 0.f;

    for (int k0 = 0; k0 < 192; k0 += 16) {
        // A tile: 128 tokens x 16 channels (gathered from x)
#pragma unroll
        for (int it = 0; it < 2; it++) {
            int fid = tid + it * 256;       // float4 id, 512 total
            int row = fid >> 2;
            int kq  = (fid & 3) * 4;
            int tok = t0 + row;
            const float4 a = *(const float4*)&x[winbase + (tok >> 4)*49152
                                                + (tok & 15)*192 + k0 + kq];
            As[kq+0][row] = a.x; As[kq+1][row] = a.y;
            As[kq+2][row] = a.z; As[kq+3][row] = a.w;
        }
        // B tile: 64 n-rows x 16 k
        {
            int nrow = tid >> 2;
            int kq   = (tid & 3) * 4;
            const float4 w = *(const float4*)&wqkv[(n0+nrow)*192 + k0 + kq];
            Bs[kq+0][nrow] = w.x; Bs[kq+1][nrow] = w.y;
            Bs[kq+2][nrow] = w.z; Bs[kq+3][nrow] = w.w;
        }
        __syncthreads();
#pragma unroll
        for (int k = 0; k < 16; k++) {
            float a[8], bv[4];
#pragma unroll
            for (int i = 0; i < 8; i++) a[i] = As[k][tm+i];
#pragma unroll
            for (int j = 0; j < 4; j++) bv[j] = Bs[k][tn+j];
#pragma unroll
            for (int i = 0; i < 8; i++)
#pragma unroll
                for (int j = 0; j < 4; j++) acc[i][j] += a[i] * bv[j];
        }
        __syncthreads();
    }

    float* obuf = (ntile < 3) ? g_q : (ntile < 6 ? g_k : g_v);
    const int c0 = n0 % 192;
#pragma unroll
    for (int i = 0; i < 8; i++) {
        int tok = t0 + tm + i;
        float* orow = obuf + win*WIN_ELEMS + tok*192 + c0 + tn;
#pragma unroll
        for (int j = 0; j < 4; j++)
            orow[j] = acc[i][j] + bqkv[n0 + tn + j];
    }
}

// ---------------------------------------------------------------------------
// K2: LePE depthwise 3x3 conv (SAME, zero pad) on v reinterpreted as
// [win][c][16][16] (flat buffer reinterpretation). One CTA = (window, 32 ch).
// ---------------------------------------------------------------------------
__global__ __launch_bounds__(256) void lepe_kernel(
    const float* __restrict__ wpe,
    const float* __restrict__ bpe)
{
    __shared__ float sm[18][18];
    const int win = blockIdx.x;
    const int c0  = blockIdx.y * 32;
    const int tid = threadIdx.x;
    const int pi  = tid >> 4;
    const int pj  = tid & 15;

    // zero full tile (borders remain zero across channel iterations)
    for (int e = tid; e < 18*18; e += 256) ((float*)sm)[e] = 0.f;
    __syncthreads();

    const float* vwin = g_v    + win*WIN_ELEMS;
    float*       lwin = g_lepe + win*WIN_ELEMS;

    for (int cc = 0; cc < 32; cc++) {
        const int c = c0 + cc;
        float val = vwin[c*256 + tid];
        float w[9];
#pragma unroll
        for (int t = 0; t < 9; t++) w[t] = wpe[c*9 + t];
        sm[pi+1][pj+1] = val;
        __syncthreads();
        float s = bpe[c];
#pragma unroll
        for (int ky = 0; ky < 3; ky++)
#pragma unroll
            for (int kx = 0; kx < 3; kx++)
                s += sm[pi+ky][pj+kx] * w[ky*3 + kx];
        lwin[c*256 + tid] = s;
        __syncthreads();
    }
}

// ---------------------------------------------------------------------------
// K3: per-window attention, fused. CTA = (window, 64-row q block).
// Phase 1: S = Q K^T (64x256), regs -> smem. Phase 2: row softmax.
// Phase 3: O = P V (64x192) + lepe -> g_oa.
// smem: Qs 48KB + Ss 64KB + K/V staging 24KB = 136KB dynamic.
// ---------------------------------------------------------------------------
__global__ __launch_bounds__(256) void attn_kernel()
{
    extern __shared__ float smx[];
    float* Qs = smx;                       // 64*192
    float* Ss = smx + 64*192;              // 64*256
    float* KV = Ss  + 64*256;              // max(16*256, 32*192)

    const int tid = threadIdx.x;
    const int win = blockIdx.x >> 2;
    const int t0  = (blockIdx.x & 3) * 64;

    const float* qw = g_q + win*WIN_ELEMS + t0*192;
    const float* kw = g_k + win*WIN_ELEMS;
    const float* vw = g_v + win*WIN_ELEMS;

    // load Q block (64x192) coalesced float4
#pragma unroll
    for (int i = 0; i < 12; i++) {
        int f = tid + i*256;
        ((float4*)Qs)[f] = ((const float4*)qw)[f];
    }
    __syncthreads();

    const int tm  = (tid >> 4) * 4;        // 4 rows
    const int tn0 = tid & 15;              // strided-n base

    // ---- Phase 1: S = Q K^T ----
    float s[4][16];
#pragma unroll
    for (int i = 0; i < 4; i++)
#pragma unroll
        for (int j = 0; j < 16; j++) s[i][j] = 0.f;

    for (int k0 = 0; k0 < 192; k0 += 16) {
        float* Ks = KV;                    // Ks[16][256]
        const float4* src = (const float4*)(kw + tid*192 + k0);
#pragma unroll
        for (int q = 0; q < 4; q++) {
            float4 v4 = src[q];
            Ks[(q*4+0)*256 + tid] = v4.x;
            Ks[(q*4+1)*256 + tid] = v4.y;
            Ks[(q*4+2)*256 + tid] = v4.z;
            Ks[(q*4+3)*256 + tid] = v4.w;
        }
        __syncthreads();
#pragma unroll
        for (int k = 0; k < 16; k++) {
            float a[4], b[16];
#pragma unroll
            for (int i = 0; i < 4; i++) a[i] = Qs[(tm+i)*192 + k0 + k];
#pragma unroll
            for (int j = 0; j < 16; j++) b[j] = Ks[k*256 + tn0 + 16*j];
#pragma unroll
            for (int i = 0; i < 4; i++)
#pragma unroll
                for (int j = 0; j < 16; j++) s[i][j] += a[i] * b[j];
        }
        __syncthreads();
    }

    const float scale = 0.07216878364870323f; // 1/sqrt(192)
#pragma unroll
    for (int i = 0; i < 4; i++)
#pragma unroll
        for (int j = 0; j < 16; j++)
            Ss[(tm+i)*256 + tn0 + 16*j] = s[i][j] * scale;
    __syncthreads();

    // ---- Phase 2: softmax, one warp per row (conflict-free) ----
    {
        const int warp = tid >> 5, lane = tid & 31;
        for (int r = warp; r < 64; r += 8) {
            float* row = Ss + r*256;
            float e[8];
            float mx = -1e30f;
#pragma unroll
            for (int q = 0; q < 8; q++) { e[q] = row[lane + 32*q]; mx = fmaxf(mx, e[q]); }
#pragma unroll
            for (int o = 16; o > 0; o >>= 1) mx = fmaxf(mx, __shfl_xor_sync(0xffffffffu, mx, o));
            float sum = 0.f;
#pragma unroll
            for (int q = 0; q < 8; q++) { e[q] = __expf(e[q] - mx); sum += e[q]; }
#pragma unroll
            for (int o = 16; o > 0; o >>= 1) sum += __shfl_xor_sync(0xffffffffu, sum, o);
            float inv = 1.f / sum;
#pragma unroll
            for (int q = 0; q < 8; q++) row[lane + 32*q] = e[q] * inv;
        }
    }
    __syncthreads();

    // ---- Phase 3: O = P V ----
    float o[4][12];
#pragma unroll
    for (int i = 0; i < 4; i++)
#pragma unroll
        for (int j = 0; j < 12; j++) o[i][j] = 0.f;

    for (int kt = 0; kt < 8; kt++) {
        float* Vs = KV;                    // Vs[32][192]
        const float4* src = (const float4*)(vw + kt*32*192);
#pragma unroll
        for (int i = 0; i < 6; i++) {
            int f = tid + i*256;
            ((float4*)Vs)[f] = src[f];
        }
        __syncthreads();
#pragma unroll
        for (int k = 0; k < 32; k++) {
            float a[4], b[12];
#pragma unroll
            for (int i = 0; i < 4; i++) a[i] = Ss[(tm+i)*256 + kt*32 + k];
#pragma unroll
            for (int j = 0; j < 12; j++) b[j] = Vs[k*192 + tn0 + 16*j];
#pragma unroll
            for (int i = 0; i < 4; i++)
#pragma unroll
                for (int j = 0; j < 12; j++) o[i][j] += a[i] * b[j];
        }
        __syncthreads();
    }

    // epilogue: + lepe (flat reinterpretation), write attention output
    const float* lw = g_lepe + win*WIN_ELEMS;
    float*       ow = g_oa   + win*WIN_ELEMS;
#pragma unroll
    for (int i = 0; i < 4; i++) {
        int t = t0 + tm + i;
#pragma unroll
        for (int j = 0; j < 12; j++) {
            int c = tn0 + 16*j;
            ow[t*192 + c] = o[i][j] + lw[t*192 + c];
        }
    }
}

// ---------------------------------------------------------------------------
// K4: output projection + reverse-window scatter.
// M = 262144, N = 192, K = 192, A = g_oa (contiguous). Tile 128x64x16.
// ---------------------------------------------------------------------------
__global__ __launch_bounds__(256) void proj_kernel(
    const float* __restrict__ wout,
    const float* __restrict__ bout,
    float* __restrict__ out)
{
    __shared__ float As[16][129];
    __shared__ float Bs[16][65];

    const int mtile = blockIdx.x;          // 0..2047
    const int ntile = blockIdx.y;          // 0..2
    const int m0 = mtile * 128;
    const int n0 = ntile * 64;
    const int tid = threadIdx.x;
    const int tm = (tid >> 4) * 8;
    const int tn = (tid & 15) * 4;

    float acc[8][4];
#pragma unroll
    for (int i = 0; i < 8; i++)
#pragma unroll
        for (int j = 0; j < 4; j++) acc[i][j] = 0.f;

    for (int k0 = 0; k0 < 192; k0 += 16) {
#pragma unroll
        for (int it = 0; it < 2; it++) {
            int fid = tid + it * 256;
            int row = fid >> 2;
            int kq  = (fid & 3) * 4;
            const float4 a = *(const float4*)&g_oa[(m0+row)*192 + k0 + kq];
            As[kq+0][row] = a.x; As[kq+1][row] = a.y;
            As[kq+2][row] = a.z; As[kq+3][row] = a.w;
        }
        {
            int nrow = tid >> 2;
            int kq   = (tid & 3) * 4;
            const float4 w = *(const float4*)&wout[(n0+nrow)*192 + k0 + kq];
            Bs[kq+0][nrow] = w.x; Bs[kq+1][nrow] = w.y;
            Bs[kq+2][nrow] = w.z; Bs[kq+3][nrow] = w.w;
        }
        __syncthreads();
#pragma unroll
        for (int k = 0; k < 16; k++) {
            float a[8], bv[4];
#pragma unroll
            for (int i = 0; i < 8; i++) a[i] = As[k][tm+i];
#pragma unroll
            for (int j = 0; j < 4; j++) bv[j] = Bs[k][tn+j];
#pragma unroll
            for (int i = 0; i < 8; i++)
#pragma unroll
                for (int j = 0; j < 4; j++) acc[i][j] += a[i] * bv[j];
        }
        __syncthreads();
    }

#pragma unroll
    for (int i = 0; i < 8; i++) {
        const int m   = m0 + tm + i;
        const int win = m >> 8;
        const int t   = m & 255;
        const int bb  = win >> 8;
        const int hy  = (win >> 4) & 15;
        const int wx  = win & 15;
        const int ty  = t >> 4;
        const int tx  = t & 15;
        const int base = bb*12582912 + hy*786432 + ty*49152 + wx*3072 + tx*192;
#pragma unroll
        for (int j = 0; j < 4; j++) {
            int n = n0 + tn + j;
            out[base + n] = acc[i][j] + bout[n];
        }
    }
}

// ---------------------------------------------------------------------------
extern "C" void kernel_launch(void* const* d_in, const int* in_sizes, int n_in,
                              void* d_out, int out_size)
{
    const float* x     = (const float*)d_in[0];
    const float* wqkv  = (const float*)d_in[1];
    const float* bqkv  = (const float*)d_in[2];
    const float* wpe   = (const float*)d_in[3];
    const float* bpe   = (const float*)d_in[4];
    const float* wout  = (const float*)d_in[5];
    const float* bout  = (const float*)d_in[6];
    float* out = (float*)d_out;

    const int attn_smem = (64*192 + 64*256 + 32*192) * (int)sizeof(float); // 139264
    cudaFuncSetAttribute(attn_kernel, cudaFuncAttributeMaxDynamicSharedMemorySize, attn_smem);

    qkv_kernel <<<dim3(2048, 9), 256>>>(x, wqkv, bqkv);
    lepe_kernel<<<dim3(1024, 6), 256>>>(wpe, bpe);
    attn_kernel<<<4096, 256, attn_smem>>>();
    proj_kernel<<<dim3(2048, 3), 256>>>(wout, bout, out);
}

// round 4
// speedup vs baseline: 4.7879x; 4.7879x over previous
#include <cuda_runtime.h>
#include <cuda_fp16.h>
#include <cstdint>

#define NW        1024
#define WIN_ELEMS (256*192)
#define LDH       200
#define LDP       264

__device__ __align__(16) __half g_q[NW*WIN_ELEMS];
__device__ __align__(16) __half g_k[NW*WIN_ELEMS];
__device__ __align__(16) __half g_v[NW*WIN_ELEMS];
__device__ __align__(16) float  g_lepe[NW*WIN_ELEMS];
__device__ __align__(16) __half g_oa[NW*WIN_ELEMS];

__device__ __forceinline__ unsigned smem_u32(const void* ptr)
{
    return (unsigned)__cvta_generic_to_shared(ptr);
}

__device__ __forceinline__ void ldsm4(unsigned* r, unsigned a)
{
    asm volatile("ldmatrix.sync.aligned.m8n8.x4.shared.b16 {%0,%1,%2,%3}, [%4];" : "=r"(r[0]), "=r"(r[1]), "=r"(r[2]), "=r"(r[3]) : "r"(a));
}

__device__ __forceinline__ void ldsm4t(unsigned* r, unsigned a)
{
    asm volatile("ldmatrix.sync.aligned.m8n8.x4.trans.shared.b16 {%0,%1,%2,%3}, [%4];" : "=r"(r[0]), "=r"(r[1]), "=r"(r[2]), "=r"(r[3]) : "r"(a));
}

__device__ __forceinline__ void mma16816(float* d, const unsigned* a, const unsigned* b)
{
    asm volatile("mma.sync.aligned.m16n8k16.row.col.f32.f16.f16.f32 {%0,%1,%2,%3},{%4,%5,%6,%7},{%8,%9},{%0,%1,%2,%3};" : "+f"(d[0]), "+f"(d[1]), "+f"(d[2]), "+f"(d[3]) : "r"(a[0]), "r"(a[1]), "r"(a[2]), "r"(a[3]), "r"(b[0]), "r"(b[1]));
}

// ---------------------------------------------------------------------------
// K1: QKV projection (HMMA). One CTA per window (M=256), nt loops q/k/v.
// ---------------------------------------------------------------------------
__global__ __launch_bounds__(256) void qkv_kernel(const float* __restrict__ x, const float* __restrict__ wqkv, const float* __restrict__ bqkv)
{
    extern __shared__ __half sh_qkv[];
    __half* As = sh_qkv;
    __half* Bs = sh_qkv + 256*LDH;

    const int tid  = threadIdx.x;
    const int warp = tid >> 5;
    const int lane = tid & 31;
    const int win  = blockIdx.x;
    const int bb   = win >> 8;
    const int hy   = (win >> 4) & 15;
    const int wx   = win & 15;
    const int winbase = bb*12582912 + hy*786432 + wx*3072;
    const int grp  = lane >> 2;
    const int t2   = (lane & 3) * 2;
    const int wm   = (warp >> 1) * 32;
    const int wn   = (warp & 1) * 96;

    #pragma unroll
    for (int it = 0; it < 48; it++) {
        int i   = tid + it*256;
        int row = i / 48;
        int c   = (i % 48) * 4;
        const float* src = x + winbase + (row>>4)*49152 + (row&15)*192 + c;
        float4 av = *(const float4*)src;
        __half2* dp = (__half2*)(As + row*LDH + c);
        dp[0] = __floats2half2_rn(av.x, av.y);
        dp[1] = __floats2half2_rn(av.z, av.w);
    }

    for (int nt = 0; nt < 3; nt++) {
        __syncthreads();
        const float* wsrc = wqkv + nt*192*192;
        #pragma unroll
        for (int it = 0; it < 36; it++) {
            int i   = tid + it*256;
            int row = i / 48;
            int c   = (i % 48) * 4;
            float4 wv = *(const float4*)(wsrc + row*192 + c);
            __half2* dp = (__half2*)(Bs + row*LDH + c);
            dp[0] = __floats2half2_rn(wv.x, wv.y);
            dp[1] = __floats2half2_rn(wv.z, wv.w);
        }
        __syncthreads();

        __half* obuf = g_v;
        if (nt == 0) { obuf = g_q; }
        if (nt == 1) { obuf = g_k; }
        const float* bp = bqkv + nt*192;

        for (int mt = 0; mt < 2; mt++) {
            const __half* Am = As + mt*128*LDH;
            float acc[2][12][4];
            for (int i = 0; i < 2; i++) {
                for (int j = 0; j < 12; j++) {
                    for (int q = 0; q < 4; q++) { acc[i][j][q] = 0.f; }
                }
            }

            #pragma unroll
            for (int k0 = 0; k0 < 192; k0 += 16) {
                unsigned afr[2][4];
                #pragma unroll
                for (int mi = 0; mi < 2; mi++) {
                    unsigned aaddr = smem_u32(Am + (wm + mi*16 + (lane&15))*LDH + k0 + (lane>>4)*8);
                    ldsm4(afr[mi], aaddr);
                }
                #pragma unroll
                for (int nj2 = 0; nj2 < 6; nj2++) {
                    unsigned bfr[4];
                    unsigned baddr = smem_u32(Bs + (wn + nj2*16 + (lane&7) + ((lane>>4)<<3))*LDH + k0 + ((lane>>3)&1)*8);
                    ldsm4(bfr, baddr);
                    #pragma unroll
                    for (int mi = 0; mi < 2; mi++) {
                        mma16816(acc[mi][nj2*2],   afr[mi], bfr);
                        mma16816(acc[mi][nj2*2+1], afr[mi], bfr+2);
                    }
                }
            }

            #pragma unroll
            for (int mi = 0; mi < 2; mi++) {
                #pragma unroll
                for (int rh = 0; rh < 2; rh++) {
                    int tok = mt*128 + wm + mi*16 + grp + rh*8;
                    __half* orow = obuf + win*WIN_ELEMS + tok*192;
                    #pragma unroll
                    for (int nj = 0; nj < 12; nj++) {
                        int c = wn + nj*8 + t2;
                        float v0 = acc[mi][nj][rh*2+0] + bp[c];
                        float v1 = acc[mi][nj][rh*2+1] + bp[c+1];
                        *(__half2*)(orow + c) = __floats2half2_rn(v0, v1);
                    }
                }
            }
        }
    }
}

// ---------------------------------------------------------------------------
// K2: LePE depthwise 3x3 on v reinterpreted as [win][c][16][16].
// ---------------------------------------------------------------------------
__global__ __launch_bounds__(256) void lepe_kernel(const float* __restrict__ wpe, const float* __restrict__ bpe)
{
    __shared__ float tile[18][18];
    const int win = blockIdx.x;
    const int c0  = blockIdx.y * 32;
    const int tid = threadIdx.x;
    const int pi  = tid >> 4;
    const int pj  = tid & 15;

    for (int e = tid; e < 18*18; e += 256) {
        ((float*)tile)[e] = 0.f;
    }
    __syncthreads();

    const __half* vwin = g_v    + win*WIN_ELEMS;
    float*        lwin = g_lepe + win*WIN_ELEMS;

    for (int cc = 0; cc < 32; cc++) {
        const int c = c0 + cc;
        float val = __half2float(vwin[c*256 + tid]);
        float wv[9];
        #pragma unroll
        for (int t = 0; t < 9; t++) {
            wv[t] = wpe[c*9 + t];
        }
        tile[pi+1][pj+1] = val;
        __syncthreads();
        float s = bpe[c];
        #pragma unroll
        for (int ky = 0; ky < 3; ky++) {
            #pragma unroll
            for (int kx = 0; kx < 3; kx++) {
                s += tile[pi+ky][pj+kx] * wv[ky*3 + kx];
            }
        }
        lwin[c*256 + tid] = s;
        __syncthreads();
    }
}

// ---------------------------------------------------------------------------
// K3: fused attention (HMMA). CTA = half window (128 q rows x 256 kv).
// ---------------------------------------------------------------------------
__global__ __launch_bounds__(256) void attn_kernel()
{
    extern __shared__ char sh_attn[];
    __half* Qs    = (__half*)sh_attn;
    __half* Ks    = (__half*)(sh_attn + 51200);
    __half* Ps    = (__half*)sh_attn;
    __half* Vs    = (__half*)(sh_attn + 67584);
    float*  s_max = (float*)(sh_attn + 169984);
    float*  s_sum = (float*)(sh_attn + 172032);

    const int tid  = threadIdx.x;
    const int warp = tid >> 5;
    const int lane = tid & 31;
    const int win  = blockIdx.x >> 1;
    const int t0   = (blockIdx.x & 1) * 128;
    const int grp  = lane >> 2;
    const int t2   = (lane & 3) * 2;

    const __half* qg = g_q + win*WIN_ELEMS + t0*192;
    const __half* kg = g_k + win*WIN_ELEMS;
    const __half* vg = g_v + win*WIN_ELEMS;

    #pragma unroll
    for (int it = 0; it < 12; it++) {
        int i   = tid + it*256;
        int row = i / 24;
        int c16 = i % 24;
        *(uint4*)(Qs + row*LDH + c16*8) = *(const uint4*)(qg + row*192 + c16*8);
    }
    #pragma unroll
    for (int it = 0; it < 24; it++) {
        int i   = tid + it*256;
        int row = i / 24;
        int c16 = i % 24;
        *(uint4*)(Ks + row*LDH + c16*8) = *(const uint4*)(kg + row*192 + c16*8);
    }
    __syncthreads();

    // S = Q K^T : warp grid 2M x 4N, warp tile 64x64
    const int swm = (warp >> 2) * 64;
    const int swn = (warp & 3) * 64;
    float acc[4][8][4];
    for (int i = 0; i < 4; i++) {
        for (int j = 0; j < 8; j++) {
            for (int q = 0; q < 4; q++) { acc[i][j][q] = 0.f; }
        }
    }

    #pragma unroll
    for (int k0 = 0; k0 < 192; k0 += 16) {
        unsigned afr[4][4];
        #pragma unroll
        for (int mi = 0; mi < 4; mi++) {
            unsigned aaddr = smem_u32(Qs + (swm + mi*16 + (lane&15))*LDH + k0 + (lane>>4)*8);
            ldsm4(afr[mi], aaddr);
        }
        #pragma unroll
        for (int nj2 = 0; nj2 < 4; nj2++) {
            unsigned bfr[4];
            unsigned baddr = smem_u32(Ks + (swn + nj2*16 + (lane&7) + ((lane>>4)<<3))*LDH + k0 + ((lane>>3)&1)*8);
            ldsm4(bfr, baddr);
            #pragma unroll
            for (int mi = 0; mi < 4; mi++) {
                mma16816(acc[mi][nj2*2],   afr[mi], bfr);
                mma16816(acc[mi][nj2*2+1], afr[mi], bfr+2);
            }
        }
    }

    const float scale = 0.07216878364870323f;
    #pragma unroll
    for (int mi = 0; mi < 4; mi++) {
        #pragma unroll
        for (int nj = 0; nj < 8; nj++) {
            #pragma unroll
            for (int q = 0; q < 4; q++) {
                acc[mi][nj][q] *= scale;
            }
        }
    }

    // per-row max partials (4 n-strip warps per row)
    #pragma unroll
    for (int mi = 0; mi < 4; mi++) {
        #pragma unroll
        for (int rh = 0; rh < 2; rh++) {
            float m = -1e30f;
            #pragma unroll
            for (int nj = 0; nj < 8; nj++) {
                m = fmaxf(m, fmaxf(acc[mi][nj][rh*2], acc[mi][nj][rh*2+1]));
            }
            m = fmaxf(m, __shfl_xor_sync(0xffffffffu, m, 1));
            m = fmaxf(m, __shfl_xor_sync(0xffffffffu, m, 2));
            if ((lane & 3) == 0) {
                s_max[(swm + mi*16 + grp + rh*8)*4 + (warp & 3)] = m;
            }
        }
    }
    __syncthreads();

    // load V (Qs/Ks regions dead now)
    #pragma unroll
    for (int it = 0; it < 24; it++) {
        int i   = tid + it*256;
        int row = i / 24;
        int c16 = i % 24;
        *(uint4*)(Vs + row*LDH + c16*8) = *(const uint4*)(vg + row*192 + c16*8);
    }

    // exp (unnormalized), store P fp16, per-row sum partials
    #pragma unroll
    for (int mi = 0; mi < 4; mi++) {
        #pragma unroll
        for (int rh = 0; rh < 2; rh++) {
            int row = swm + mi*16 + grp + rh*8;
            float m01 = fmaxf(s_max[row*4+0], s_max[row*4+1]);
            float m23 = fmaxf(s_max[row*4+2], s_max[row*4+3]);
            float rmax = fmaxf(m01, m23);
            float s = 0.f;
            #pragma unroll
            for (int nj = 0; nj < 8; nj++) {
                float e0 = __expf(acc[mi][nj][rh*2+0] - rmax);
                float e1 = __expf(acc[mi][nj][rh*2+1] - rmax);
                s += e0 + e1;
                *(__half2*)(Ps + row*LDP + swn + nj*8 + t2) = __floats2half2_rn(e0, e1);
            }
            s += __shfl_xor_sync(0xffffffffu, s, 1);
            s += __shfl_xor_sync(0xffffffffu, s, 2);
            if ((lane & 3) == 0) {
                s_sum[row*4 + (warp & 3)] = s;
            }
        }
    }
    __syncthreads();

    // O = P V : warp grid 4M x 2N, warp tile 32x96
    const int pwm = (warp >> 1) * 32;
    const int pwn = (warp & 1) * 96;
    float oacc[2][12][4];
    for (int i = 0; i < 2; i++) {
        for (int j = 0; j < 12; j++) {
            for (int q = 0; q < 4; q++) { oacc[i][j][q] = 0.f; }
        }
    }

    #pragma unroll
    for (int k0 = 0; k0 < 256; k0 += 16) {
        unsigned afr[2][4];
        #pragma unroll
        for (int mi = 0; mi < 2; mi++) {
            unsigned aaddr = smem_u32(Ps + (pwm + mi*16 + (lane&15))*LDP + k0 + (lane>>4)*8);
            ldsm4(afr[mi], aaddr);
        }
        #pragma unroll
        for (int nj2 = 0; nj2 < 6; nj2++) {
            unsigned bfr[4];
            unsigned baddr = smem_u32(Vs + (k0 + (lane&7) + ((lane>>3)&1)*8)*LDH + pwn + nj2*16 + (lane>>4)*8);
            ldsm4t(bfr, baddr);
            #pragma unroll
            for (int mi = 0; mi < 2; mi++) {
                mma16816(oacc[mi][nj2*2],   afr[mi], bfr);
                mma16816(oacc[mi][nj2*2+1], afr[mi], bfr+2);
            }
        }
    }

    // epilogue: normalize by rowsum, add lepe, write half
    const float* lw = g_lepe + win*WIN_ELEMS;
    __half*      ow = g_oa   + win*WIN_ELEMS;
    #pragma unroll
    for (int mi = 0; mi < 2; mi++) {
        #pragma unroll
        for (int rh = 0; rh < 2; rh++) {
            int rl = pwm + mi*16 + grp + rh*8;
            float tot = s_sum[rl*4+0] + s_sum[rl*4+1] + s_sum[rl*4+2] + s_sum[rl*4+3];
            float inv = 1.f / tot;
            int tok = t0 + rl;
            #pragma unroll
            for (int nj = 0; nj < 12; nj++) {
                int c = pwn + nj*8 + t2;
                float2 lp = *(const float2*)(lw + tok*192 + c);
                float v0 = oacc[mi][nj][rh*2+0]*inv + lp.x;
                float v1 = oacc[mi][nj][rh*2+1]*inv + lp.y;
                *(__half2*)(ow + tok*192 + c) = __floats2half2_rn(v0, v1);
            }
        }
    }
}

// ---------------------------------------------------------------------------
// K4: output projection (HMMA) + reverse-window scatter. CTA = 256 rows.
// ---------------------------------------------------------------------------
__global__ __launch_bounds__(256) void proj_kernel(const float* __restrict__ wout, const float* __restrict__ bout, float* __restrict__ out)
{
    extern __shared__ __half sh_prj[];
    __half* As = sh_prj;
    __half* Bs = sh_prj + 256*LDH;

    const int tid  = threadIdx.x;
    const int warp = tid >> 5;
    const int lane = tid & 31;
    const int m0   = blockIdx.x * 256;
    const int grp  = lane >> 2;
    const int t2   = (lane & 3) * 2;
    const int wm   = (warp >> 1) * 32;
    const int wn   = (warp & 1) * 96;

    #pragma unroll
    for (int it = 0; it < 24; it++) {
        int i   = tid + it*256;
        int row = i / 24;
        int c16 = i % 24;
        *(uint4*)(As + row*LDH + c16*8) = *(const uint4*)(g_oa + (m0+row)*192 + c16*8);
    }
    #pragma unroll
    for (int it = 0; it < 36; it++) {
        int i   = tid + it*256;
        int row = i / 48;
        int c   = (i % 48) * 4;
        float4 wv = *(const float4*)(wout + row*192 + c);
        __half2* dp = (__half2*)(Bs + row*LDH + c);
        dp[0] = __floats2half2_rn(wv.x, wv.y);
        dp[1] = __floats2half2_rn(wv.z, wv.w);
    }
    __syncthreads();

    for (int mt = 0; mt < 2; mt++) {
        const __half* Am = As + mt*128*LDH;
        float acc[2][12][4];
        for (int i = 0; i < 2; i++) {
            for (int j = 0; j < 12; j++) {
                for (int q = 0; q < 4; q++) { acc[i][j][q] = 0.f; }
            }
        }

        #pragma unroll
        for (int k0 = 0; k0 < 192; k0 += 16) {
            unsigned afr[2][4];
            #pragma unroll
            for (int mi = 0; mi < 2; mi++) {
                unsigned aaddr = smem_u32(Am + (wm + mi*16 + (lane&15))*LDH + k0 + (lane>>4)*8);
                ldsm4(afr[mi], aaddr);
            }
            #pragma unroll
            for (int nj2 = 0; nj2 < 6; nj2++) {
                unsigned bfr[4];
                unsigned baddr = smem_u32(Bs + (wn + nj2*16 + (lane&7) + ((lane>>4)<<3))*LDH + k0 + ((lane>>3)&1)*8);
                ldsm4(bfr, baddr);
                #pragma unroll
                for (int mi = 0; mi < 2; mi++) {
                    mma16816(acc[mi][nj2*2],   afr[mi], bfr);
                    mma16816(acc[mi][nj2*2+1], afr[mi], bfr+2);
                }
            }
        }

        #pragma unroll
        for (int mi = 0; mi < 2; mi++) {
            #pragma unroll
            for (int rh = 0; rh < 2; rh++) {
                int m  = m0 + mt*128 + wm + mi*16 + grp + rh*8;
                int wi = m >> 8;
                int t  = m & 255;
                int bb = wi >> 8;
                int hy = (wi >> 4) & 15;
                int wx = wi & 15;
                int ty = t >> 4;
                int tx = t & 15;
                int base = bb*12582912 + hy*786432 + ty*49152 + wx*3072 + tx*192;
                #pragma unroll
                for (int nj = 0; nj < 12; nj++) {
                    int c = wn + nj*8 + t2;
                    float2 o2;
                    o2.x = acc[mi][nj][rh*2+0] + bout[c];
                    o2.y = acc[mi][nj][rh*2+1] + bout[c+1];
                    *(float2*)(out + base + c) = o2;
                }
            }
        }
    }
}

// ---------------------------------------------------------------------------
extern "C" void kernel_launch(void* const* d_in, const int* in_sizes, int n_in,
                              void* d_out, int out_size)
{
    const float* x    = (const float*)d_in[0];
    const float* wqkv = (const float*)d_in[1];
    const float* bqkv = (const float*)d_in[2];
    const float* wpe  = (const float*)d_in[3];
    const float* bpe  = (const float*)d_in[4];
    const float* wout = (const float*)d_in[5];
    const float* bout = (const float*)d_in[6];
    float* out = (float*)d_out;

    const int sm_gemm = (256 + 192) * LDH * 2;
    const int sm_attn = 174080;
    cudaFuncSetAttribute(qkv_kernel,  cudaFuncAttributeMaxDynamicSharedMemorySize, sm_gemm);
    cudaFuncSetAttribute(proj_kernel, cudaFuncAttributeMaxDynamicSharedMemorySize, sm_gemm);
    cudaFuncSetAttribute(attn_kernel, cudaFuncAttributeMaxDynamicSharedMemorySize, sm_attn);

    qkv_kernel <<<1024, 256, sm_gemm>>>(x, wqkv, bqkv);
    lepe_kernel<<<dim3(1024, 6), 256>>>(wpe, bpe);
    attn_kernel<<<2048, 256, sm_attn>>>();
    proj_kernel<<<1024, 256, sm_gemm>>>(wout, bout, out);
}

// round 5
// speedup vs baseline: 5.4019x; 1.1282x over previous
#include <cuda_runtime.h>
#include <cuda_fp16.h>
#include <cstdint>

#define NW        1024
#define WIN_ELEMS (256*192)
#define LDH       200
#define LDP       264

__device__ __align__(16) __half g_q[NW*WIN_ELEMS];
__device__ __align__(16) __half g_k[NW*WIN_ELEMS];
__device__ __align__(16) __half g_v[NW*WIN_ELEMS];
__device__ __align__(16) float  g_lepe[NW*WIN_ELEMS];
__device__ __align__(16) __half g_oa[NW*WIN_ELEMS];

__device__ __forceinline__ unsigned smem_u32(const void* ptr)
{
    return (unsigned)__cvta_generic_to_shared(ptr);
}

__device__ __forceinline__ void ldsm4(unsigned* r, unsigned a)
{
    asm volatile("ldmatrix.sync.aligned.m8n8.x4.shared.b16 {%0,%1,%2,%3}, [%4];" : "=r"(r[0]), "=r"(r[1]), "=r"(r[2]), "=r"(r[3]) : "r"(a));
}

__device__ __forceinline__ void ldsm4t(unsigned* r, unsigned a)
{
    asm volatile("ldmatrix.sync.aligned.m8n8.x4.trans.shared.b16 {%0,%1,%2,%3}, [%4];" : "=r"(r[0]), "=r"(r[1]), "=r"(r[2]), "=r"(r[3]) : "r"(a));
}

__device__ __forceinline__ void mma16816(float* d, const unsigned* a, const unsigned* b)
{
    asm volatile("mma.sync.aligned.m16n8k16.row.col.f32.f16.f16.f32 {%0,%1,%2,%3},{%4,%5,%6,%7},{%8,%9},{%0,%1,%2,%3};" : "+f"(d[0]), "+f"(d[1]), "+f"(d[2]), "+f"(d[3]) : "r"(a[0]), "r"(a[1]), "r"(a[2]), "r"(a[3]), "r"(b[0]), "r"(b[1]));
}

// ---------------------------------------------------------------------------
// K1: QKV projection (HMMA). One CTA per window (M=256), 512 threads.
// Warp grid per 128-row half: 4M x 4N (warp tile 32x48).
// ---------------------------------------------------------------------------
__global__ __launch_bounds__(512) void qkv_kernel(const float* __restrict__ x, const float* __restrict__ wqkv, const float* __restrict__ bqkv)
{
    extern __shared__ __half sh_qkv[];
    __half* As = sh_qkv;
    __half* Bs = sh_qkv + 256*LDH;

    const int tid  = threadIdx.x;
    const int warp = tid >> 5;
    const int lane = tid & 31;
    const int win  = blockIdx.x;
    const int bb   = win >> 8;
    const int hy   = (win >> 4) & 15;
    const int wx   = win & 15;
    const int winbase = bb*12582912 + hy*786432 + wx*3072;
    const int grp  = lane >> 2;
    const int t2   = (lane & 3) * 2;
    const int wm   = (warp >> 2) * 32;
    const int wn   = (warp & 3) * 48;

    #pragma unroll
    for (int it = 0; it < 24; it++) {
        int i   = tid + it*512;
        int row = i / 48;
        int c   = (i % 48) * 4;
        const float* src = x + winbase + (row>>4)*49152 + (row&15)*192 + c;
        float4 av = *(const float4*)src;
        __half2* dp = (__half2*)(As + row*LDH + c);
        dp[0] = __floats2half2_rn(av.x, av.y);
        dp[1] = __floats2half2_rn(av.z, av.w);
    }

    for (int nt = 0; nt < 3; nt++) {
        __syncthreads();
        const float* wsrc = wqkv + nt*192*192;
        #pragma unroll
        for (int it = 0; it < 18; it++) {
            int i   = tid + it*512;
            int row = i / 48;
            int c   = (i % 48) * 4;
            float4 wv = *(const float4*)(wsrc + row*192 + c);
            __half2* dp = (__half2*)(Bs + row*LDH + c);
            dp[0] = __floats2half2_rn(wv.x, wv.y);
            dp[1] = __floats2half2_rn(wv.z, wv.w);
        }
        __syncthreads();

        __half* obuf = g_v;
        if (nt == 0) { obuf = g_q; }
        if (nt == 1) { obuf = g_k; }
        const float* bp = bqkv + nt*192;

        for (int mt = 0; mt < 2; mt++) {
            const __half* Am = As + mt*128*LDH;
            float acc[2][6][4];
            for (int i = 0; i < 2; i++) {
                for (int j = 0; j < 6; j++) {
                    for (int q = 0; q < 4; q++) { acc[i][j][q] = 0.f; }
                }
            }

            #pragma unroll
            for (int k0 = 0; k0 < 192; k0 += 16) {
                unsigned afr[2][4];
                #pragma unroll
                for (int mi = 0; mi < 2; mi++) {
                    unsigned aaddr = smem_u32(Am + (wm + mi*16 + (lane&15))*LDH + k0 + (lane>>4)*8);
                    ldsm4(afr[mi], aaddr);
                }
                #pragma unroll
                for (int nj2 = 0; nj2 < 3; nj2++) {
                    unsigned bfr[4];
                    unsigned baddr = smem_u32(Bs + (wn + nj2*16 + (lane&7) + ((lane>>4)<<3))*LDH + k0 + ((lane>>3)&1)*8);
                    ldsm4(bfr, baddr);
                    #pragma unroll
                    for (int mi = 0; mi < 2; mi++) {
                        mma16816(acc[mi][nj2*2],   afr[mi], bfr);
                        mma16816(acc[mi][nj2*2+1], afr[mi], bfr+2);
                    }
                }
            }

            #pragma unroll
            for (int mi = 0; mi < 2; mi++) {
                #pragma unroll
                for (int rh = 0; rh < 2; rh++) {
                    int tok = mt*128 + wm + mi*16 + grp + rh*8;
                    __half* orow = obuf + win*WIN_ELEMS + tok*192;
                    #pragma unroll
                    for (int nj = 0; nj < 6; nj++) {
                        int c = wn + nj*8 + t2;
                        float v0 = acc[mi][nj][rh*2+0] + bp[c];
                        float v1 = acc[mi][nj][rh*2+1] + bp[c+1];
                        *(__half2*)(orow + c) = __floats2half2_rn(v0, v1);
                    }
                }
            }
        }
    }
}

// ---------------------------------------------------------------------------
// K2: LePE depthwise 3x3 on v reinterpreted as [win][c][16][16].
// ---------------------------------------------------------------------------
__global__ __launch_bounds__(256) void lepe_kernel(const float* __restrict__ wpe, const float* __restrict__ bpe)
{
    __shared__ float tile[18][18];
    const int win = blockIdx.x;
    const int c0  = blockIdx.y * 32;
    const int tid = threadIdx.x;
    const int pi  = tid >> 4;
    const int pj  = tid & 15;

    for (int e = tid; e < 18*18; e += 256) {
        ((float*)tile)[e] = 0.f;
    }
    __syncthreads();

    const __half* vwin = g_v    + win*WIN_ELEMS;
    float*        lwin = g_lepe + win*WIN_ELEMS;

    for (int cc = 0; cc < 32; cc++) {
        const int c = c0 + cc;
        float val = __half2float(vwin[c*256 + tid]);
        float wv[9];
        #pragma unroll
        for (int t = 0; t < 9; t++) {
            wv[t] = wpe[c*9 + t];
        }
        tile[pi+1][pj+1] = val;
        __syncthreads();
        float s = bpe[c];
        #pragma unroll
        for (int ky = 0; ky < 3; ky++) {
            #pragma unroll
            for (int kx = 0; kx < 3; kx++) {
                s += tile[pi+ky][pj+kx] * wv[ky*3 + kx];
            }
        }
        lwin[c*256 + tid] = s;
        __syncthreads();
    }
}

// ---------------------------------------------------------------------------
// K3: fused attention (HMMA). CTA = half window (128 q x 256 kv), 512 threads.
// S phase warp grid 4M x 4N (32x64); PV warp grid 4M x 4N (32x48).
// ---------------------------------------------------------------------------
__global__ __launch_bounds__(512) void attn_kernel()
{
    extern __shared__ char sh_attn[];
    __half* Qs    = (__half*)sh_attn;
    __half* Ks    = (__half*)(sh_attn + 51200);
    __half* Ps    = (__half*)sh_attn;
    __half* Vs    = (__half*)(sh_attn + 67584);
    float*  s_max = (float*)(sh_attn + 169984);
    float*  s_sum = (float*)(sh_attn + 172032);

    const int tid  = threadIdx.x;
    const int warp = tid >> 5;
    const int lane = tid & 31;
    const int win  = blockIdx.x >> 1;
    const int t0   = (blockIdx.x & 1) * 128;
    const int grp  = lane >> 2;
    const int t2   = (lane & 3) * 2;

    const __half* qg = g_q + win*WIN_ELEMS + t0*192;
    const __half* kg = g_k + win*WIN_ELEMS;
    const __half* vg = g_v + win*WIN_ELEMS;

    #pragma unroll
    for (int it = 0; it < 6; it++) {
        int i   = tid + it*512;
        int row = i / 24;
        int c16 = i % 24;
        *(uint4*)(Qs + row*LDH + c16*8) = *(const uint4*)(qg + row*192 + c16*8);
    }
    #pragma unroll
    for (int it = 0; it < 12; it++) {
        int i   = tid + it*512;
        int row = i / 24;
        int c16 = i % 24;
        *(uint4*)(Ks + row*LDH + c16*8) = *(const uint4*)(kg + row*192 + c16*8);
    }
    __syncthreads();

    // S = Q K^T : warp grid 4M x 4N, warp tile 32x64
    const int swm = (warp >> 2) * 32;
    const int swn = (warp & 3) * 64;
    float acc[2][8][4];
    for (int i = 0; i < 2; i++) {
        for (int j = 0; j < 8; j++) {
            for (int q = 0; q < 4; q++) { acc[i][j][q] = 0.f; }
        }
    }

    #pragma unroll
    for (int k0 = 0; k0 < 192; k0 += 16) {
        unsigned afr[2][4];
        #pragma unroll
        for (int mi = 0; mi < 2; mi++) {
            unsigned aaddr = smem_u32(Qs + (swm + mi*16 + (lane&15))*LDH + k0 + (lane>>4)*8);
            ldsm4(afr[mi], aaddr);
        }
        #pragma unroll
        for (int nj2 = 0; nj2 < 4; nj2++) {
            unsigned bfr[4];
            unsigned baddr = smem_u32(Ks + (swn + nj2*16 + (lane&7) + ((lane>>4)<<3))*LDH + k0 + ((lane>>3)&1)*8);
            ldsm4(bfr, baddr);
            #pragma unroll
            for (int mi = 0; mi < 2; mi++) {
                mma16816(acc[mi][nj2*2],   afr[mi], bfr);
                mma16816(acc[mi][nj2*2+1], afr[mi], bfr+2);
            }
        }
    }

    const float scale = 0.07216878364870323f;
    #pragma unroll
    for (int mi = 0; mi < 2; mi++) {
        #pragma unroll
        for (int nj = 0; nj < 8; nj++) {
            #pragma unroll
            for (int q = 0; q < 4; q++) {
                acc[mi][nj][q] *= scale;
            }
        }
    }

    // per-row max partials (4 n-strip warps per row)
    #pragma unroll
    for (int mi = 0; mi < 2; mi++) {
        #pragma unroll
        for (int rh = 0; rh < 2; rh++) {
            float m = -1e30f;
            #pragma unroll
            for (int nj = 0; nj < 8; nj++) {
                m = fmaxf(m, fmaxf(acc[mi][nj][rh*2], acc[mi][nj][rh*2+1]));
            }
            m = fmaxf(m, __shfl_xor_sync(0xffffffffu, m, 1));
            m = fmaxf(m, __shfl_xor_sync(0xffffffffu, m, 2));
            if ((lane & 3) == 0) {
                s_max[(swm + mi*16 + grp + rh*8)*4 + (warp & 3)] = m;
            }
        }
    }
    __syncthreads();

    // load V (Qs/Ks dead now)
    #pragma unroll
    for (int it = 0; it < 12; it++) {
        int i   = tid + it*512;
        int row = i / 24;
        int c16 = i % 24;
        *(uint4*)(Vs + row*LDH + c16*8) = *(const uint4*)(vg + row*192 + c16*8);
    }

    // exp (unnormalized), store P fp16, per-row sum partials
    #pragma unroll
    for (int mi = 0; mi < 2; mi++) {
        #pragma unroll
        for (int rh = 0; rh < 2; rh++) {
            int row = swm + mi*16 + grp + rh*8;
            float m01 = fmaxf(s_max[row*4+0], s_max[row*4+1]);
            float m23 = fmaxf(s_max[row*4+2], s_max[row*4+3]);
            float rmax = fmaxf(m01, m23);
            float s = 0.f;
            #pragma unroll
            for (int nj = 0; nj < 8; nj++) {
                float e0 = __expf(acc[mi][nj][rh*2+0] - rmax);
                float e1 = __expf(acc[mi][nj][rh*2+1] - rmax);
                s += e0 + e1;
                *(__half2*)(Ps + row*LDP + swn + nj*8 + t2) = __floats2half2_rn(e0, e1);
            }
            s += __shfl_xor_sync(0xffffffffu, s, 1);
            s += __shfl_xor_sync(0xffffffffu, s, 2);
            if ((lane & 3) == 0) {
                s_sum[row*4 + (warp & 3)] = s;
            }
        }
    }
    __syncthreads();

    // O = P V : warp grid 4M x 4N, warp tile 32x48
    const int pwm = (warp >> 2) * 32;
    const int pwn = (warp & 3) * 48;
    float oacc[2][6][4];
    for (int i = 0; i < 2; i++) {
        for (int j = 0; j < 6; j++) {
            for (int q = 0; q < 4; q++) { oacc[i][j][q] = 0.f; }
        }
    }

    #pragma unroll
    for (int k0 = 0; k0 < 256; k0 += 16) {
        unsigned afr[2][4];
        #pragma unroll
        for (int mi = 0; mi < 2; mi++) {
            unsigned aaddr = smem_u32(Ps + (pwm + mi*16 + (lane&15))*LDP + k0 + (lane>>4)*8);
            ldsm4(afr[mi], aaddr);
        }
        #pragma unroll
        for (int nj2 = 0; nj2 < 3; nj2++) {
            unsigned bfr[4];
            unsigned baddr = smem_u32(Vs + (k0 + (lane&7) + ((lane>>3)&1)*8)*LDH + pwn + nj2*16 + (lane>>4)*8);
            ldsm4t(bfr, baddr);
            #pragma unroll
            for (int mi = 0; mi < 2; mi++) {
                mma16816(oacc[mi][nj2*2],   afr[mi], bfr);
                mma16816(oacc[mi][nj2*2+1], afr[mi], bfr+2);
            }
        }
    }

    // epilogue: normalize by rowsum, add lepe, write half
    const float* lw = g_lepe + win*WIN_ELEMS;
    __half*      ow = g_oa   + win*WIN_ELEMS;
    #pragma unroll
    for (int mi = 0; mi < 2; mi++) {
        #pragma unroll
        for (int rh = 0; rh < 2; rh++) {
            int rl = pwm + mi*16 + grp + rh*8;
            float tot = s_sum[rl*4+0] + s_sum[rl*4+1] + s_sum[rl*4+2] + s_sum[rl*4+3];
            float inv = 1.f / tot;
            int tok = t0 + rl;
            #pragma unroll
            for (int nj = 0; nj < 6; nj++) {
                int c = pwn + nj*8 + t2;
                float2 lp = *(const float2*)(lw + tok*192 + c);
                float v0 = oacc[mi][nj][rh*2+0]*inv + lp.x;
                float v1 = oacc[mi][nj][rh*2+1]*inv + lp.y;
                *(__half2*)(ow + tok*192 + c) = __floats2half2_rn(v0, v1);
            }
        }
    }
}

// ---------------------------------------------------------------------------
// K4: output projection (HMMA) + reverse-window scatter. 512 threads.
// ---------------------------------------------------------------------------
__global__ __launch_bounds__(512) void proj_kernel(const float* __restrict__ wout, const float* __restrict__ bout, float* __restrict__ out)
{
    extern __shared__ __half sh_prj[];
    __half* As = sh_prj;
    __half* Bs = sh_prj + 256*LDH;

    const int tid  = threadIdx.x;
    const int warp = tid >> 5;
    const int lane = tid & 31;
    const int m0   = blockIdx.x * 256;
    const int grp  = lane >> 2;
    const int t2   = (lane & 3) * 2;
    const int wm   = (warp >> 2) * 32;
    const int wn   = (warp & 3) * 48;

    #pragma unroll
    for (int it = 0; it < 12; it++) {
        int i   = tid + it*512;
        int row = i / 24;
        int c16 = i % 24;
        *(uint4*)(As + row*LDH + c16*8) = *(const uint4*)(g_oa + (m0+row)*192 + c16*8);
    }
    #pragma unroll
    for (int it = 0; it < 18; it++) {
        int i   = tid + it*512;
        int row = i / 48;
        int c   = (i % 48) * 4;
        float4 wv = *(const float4*)(wout + row*192 + c);
        __half2* dp = (__half2*)(Bs + row*LDH + c);
        dp[0] = __floats2half2_rn(wv.x, wv.y);
        dp[1] = __floats2half2_rn(wv.z, wv.w);
    }
    __syncthreads();

    for (int mt = 0; mt < 2; mt++) {
        const __half* Am = As + mt*128*LDH;
        float acc[2][6][4];
        for (int i = 0; i < 2; i++) {
            for (int j = 0; j < 6; j++) {
                for (int q = 0; q < 4; q++) { acc[i][j][q] = 0.f; }
            }
        }

        #pragma unroll
        for (int k0 = 0; k0 < 192; k0 += 16) {
            unsigned afr[2][4];
            #pragma unroll
            for (int mi = 0; mi < 2; mi++) {
                unsigned aaddr = smem_u32(Am + (wm + mi*16 + (lane&15))*LDH + k0 + (lane>>4)*8);
                ldsm4(afr[mi], aaddr);
            }
            #pragma unroll
            for (int nj2 = 0; nj2 < 3; nj2++) {
                unsigned bfr[4];
                unsigned baddr = smem_u32(Bs + (wn + nj2*16 + (lane&7) + ((lane>>4)<<3))*LDH + k0 + ((lane>>3)&1)*8);
                ldsm4(bfr, baddr);
                #pragma unroll
                for (int mi = 0; mi < 2; mi++) {
                    mma16816(acc[mi][nj2*2],   afr[mi], bfr);
                    mma16816(acc[mi][nj2*2+1], afr[mi], bfr+2);
                }
            }
        }

        #pragma unroll
        for (int mi = 0; mi < 2; mi++) {
            #pragma unroll
            for (int rh = 0; rh < 2; rh++) {
                int m  = m0 + mt*128 + wm + mi*16 + grp + rh*8;
                int wi = m >> 8;
                int t  = m & 255;
                int bb = wi >> 8;
                int hy = (wi >> 4) & 15;
                int wx = wi & 15;
                int ty = t >> 4;
                int tx = t & 15;
                int base = bb*12582912 + hy*786432 + ty*49152 + wx*3072 + tx*192;
                #pragma unroll
                for (int nj = 0; nj < 6; nj++) {
                    int c = wn + nj*8 + t2;
                    float2 o2;
                    o2.x = acc[mi][nj][rh*2+0] + bout[c];
                    o2.y = acc[mi][nj][rh*2+1] + bout[c+1];
                    *(float2*)(out + base + c) = o2;
                }
            }
        }
    }
}

// ---------------------------------------------------------------------------
extern "C" void kernel_launch(void* const* d_in, const int* in_sizes, int n_in,
                              void* d_out, int out_size)
{
    const float* x    = (const float*)d_in[0];
    const float* wqkv = (const float*)d_in[1];
    const float* bqkv = (const float*)d_in[2];
    const float* wpe  = (const float*)d_in[3];
    const float* bpe  = (const float*)d_in[4];
    const float* wout = (const float*)d_in[5];
    const float* bout = (const float*)d_in[6];
    float* out = (float*)d_out;

    const int sm_gemm = (256 + 192) * LDH * 2;
    const int sm_attn = 174080;
    cudaFuncSetAttribute(qkv_kernel,  cudaFuncAttributeMaxDynamicSharedMemorySize, sm_gemm);
    cudaFuncSetAttribute(proj_kernel, cudaFuncAttributeMaxDynamicSharedMemorySize, sm_gemm);
    cudaFuncSetAttribute(attn_kernel, cudaFuncAttributeMaxDynamicSharedMemorySize, sm_attn);

    qkv_kernel <<<1024, 512, sm_gemm>>>(x, wqkv, bqkv);
    lepe_kernel<<<dim3(1024, 6), 256>>>(wpe, bpe);
    attn_kernel<<<2048, 512, sm_attn>>>();
    proj_kernel<<<1024, 512, sm_gemm>>>(wout, bout, out);
}